// round 1
// baseline (speedup 1.0000x reference)
#include <cuda_runtime.h>
#include <stdint.h>
#include <math.h>

#define Bimg 16
#define Nbox 16
#define Him  640
#define Wim  640
#define PHp  300
#define PWp  300

// ---------------------------------------------------------------------------
// JAX threefry2x32 (20 rounds), partitionable random-bits convention
// ---------------------------------------------------------------------------
__device__ __forceinline__ void tf2x32(uint32_t k0, uint32_t k1,
                                       uint32_t x0, uint32_t x1,
                                       uint32_t& o0, uint32_t& o1) {
    uint32_t ks2 = k0 ^ k1 ^ 0x1BD11BDAu;
    x0 += k0; x1 += k1;
#define TF_RND(r) { x0 += x1; x1 = (x1 << (r)) | (x1 >> (32 - (r))); x1 ^= x0; }
    TF_RND(13) TF_RND(15) TF_RND(26) TF_RND(6)
    x0 += k1;  x1 += ks2 + 1u;
    TF_RND(17) TF_RND(29) TF_RND(16) TF_RND(24)
    x0 += ks2; x1 += k0 + 2u;
    TF_RND(13) TF_RND(15) TF_RND(26) TF_RND(6)
    x0 += k0;  x1 += k1 + 3u;
    TF_RND(17) TF_RND(29) TF_RND(16) TF_RND(24)
    x0 += k1;  x1 += ks2 + 4u;
    TF_RND(13) TF_RND(15) TF_RND(26) TF_RND(6)
    x0 += ks2; x1 += k0 + 5u;
#undef TF_RND
    o0 = x0; o1 = x1;
}

// random_bits (32-bit, threefry_partitionable): bits = b0 ^ b1 at counts (hi, lo)
__device__ __forceinline__ uint32_t rbits(uint32_t k0, uint32_t k1, uint64_t idx) {
    uint32_t a, b;
    tf2x32(k0, k1, (uint32_t)(idx >> 32), (uint32_t)idx, a, b);
    return a ^ b;
}

__device__ __forceinline__ float bits_to_unit(uint32_t bits) {
    // bitcast((bits >> 9) | 0x3f800000) - 1.0  in [0,1)
    return __uint_as_float((bits >> 9) | 0x3f800000u) - 1.0f;
}

__device__ __forceinline__ float juniform(uint32_t k0, uint32_t k1, uint64_t i,
                                          float lo, float hi) {
    float f = bits_to_unit(rbits(k0, k1, i));
    return fmaxf(lo, f * (hi - lo) + lo);
}

// XLA ErfInv32 (Giles)
__device__ __forceinline__ float erfinv_xla(float x) {
    float w = -log1pf(-x * x);
    float p;
    if (w < 5.0f) {
        w -= 2.5f;
        p = 2.81022636e-08f;
        p = fmaf(p, w, 3.43273939e-07f);
        p = fmaf(p, w, -3.5233877e-06f);
        p = fmaf(p, w, -4.39150654e-06f);
        p = fmaf(p, w, 0.00021858087f);
        p = fmaf(p, w, -0.00125372503f);
        p = fmaf(p, w, -0.00417768164f);
        p = fmaf(p, w, 0.246640727f);
        p = fmaf(p, w, 1.50140941f);
    } else {
        w = sqrtf(w) - 3.0f;
        p = -0.000200214257f;
        p = fmaf(p, w, 0.000100950558f);
        p = fmaf(p, w, 0.00134934322f);
        p = fmaf(p, w, -0.00367342844f);
        p = fmaf(p, w, 0.00573950773f);
        p = fmaf(p, w, -0.0076224613f);
        p = fmaf(p, w, 0.00943887047f);
        p = fmaf(p, w, 1.00167406f);
        p = fmaf(p, w, 2.83297682f);
    }
    return p * x;
}

__device__ __forceinline__ float jnormal(uint32_t k0, uint32_t k1, uint64_t i) {
    const float lo = -0.99999994f;              // nextafter(-1, 0) in f32
    float u = juniform(k0, k1, i, lo, 1.0f);
    return 1.41421354f * erfinv_xla(u);         // f32(sqrt(2))
}

// ---------------------------------------------------------------------------
// Device scratch (no allocations allowed)
// ---------------------------------------------------------------------------
struct Geo {
    float y0i, x0i, diagi, phi, cc, top, r, ca, sa, bright;
    uint32_t k2a, k2b;
    int valid;
    int pad;
};

__device__ Geo    g_geo[Bimg][Nbox];
__device__ float  g_w[Bimg][3];
__device__ float  g_bj[Bimg][3];
__device__ float  g_s[Bimg];
__device__ double g_isum[Bimg][32];
__device__ double g_psum[Bimg][8];

// ---------------------------------------------------------------------------
// K0: all key-chain scalars + per-box geometry  (1 block, 256 threads)
// ---------------------------------------------------------------------------
__global__ void k_setup(const float* __restrict__ boxes,
                        const float* __restrict__ scale_p) {
    int t = threadIdx.x;
    if (t >= Bimg * Nbox) return;
    int b = t >> 4;
    int n = t & 15;
    float scale = scale_p[0];

    // root key(42) = (0, 42); split into B image keys: counts (0, b)
    uint32_t ib0, ib1;
    tf2x32(0u, 42u, 0u, (uint32_t)b, ib0, ib1);

    // kw, kb, kloop = split(img_key, 3): counts (0,0),(0,1),(0,2)
    uint32_t kw0, kw1, kB0, kB1, kl0, kl1;
    tf2x32(ib0, ib1, 0u, 0u, kw0, kw1);
    tf2x32(ib0, ib1, 0u, 1u, kB0, kB1);
    tf2x32(ib0, ib1, 0u, 2u, kl0, kl1);

    if (n == 0) {
        #pragma unroll
        for (int c = 0; c < 3; c++) {
            g_w[b][c]  = jnormal(kw0, kw1, (uint64_t)c) * 0.1f + 0.5f;
            g_bj[b][c] = jnormal(kB0, kB1, (uint64_t)c) * 0.01f;
        }
    }

    // key for box n; then k1,k2,k3 = split(kk, 3)
    uint32_t kn0, kn1;
    tf2x32(kl0, kl1, 0u, (uint32_t)n, kn0, kn1);
    uint32_t k10, k11, k20, k21, k30, k31;
    tf2x32(kn0, kn1, 0u, 0u, k10, k11);
    tf2x32(kn0, kn1, 0u, 1u, k20, k21);
    tf2x32(kn0, kn1, 0u, 2u, k30, k31);

    const float MAXA = (float)(20.0 * 3.14159265358979323846 / 180.0);
    float angle  = juniform(k10, k11, 0ull, -MAXA, MAXA);
    float bright = juniform(k30, k31, 0ull, -0.3f, 0.3f);

    const float* bx = boxes + ((size_t)b * Nbox + n) * 4;
    float ymin = bx[0], xmin = bx[1], ymax = bx[2], xmax = bx[3];
    float h  = ymax - ymin;
    float ww = xmax - xmin;
    float longer = fmaxf(h, ww);
    float ps   = floorf(longer * scale);
    float diag = fminf(sqrtf(2.0f) * ps, (float)Wim);
    float oy = ymin + h * 0.5f;
    float ox = xmin + ww * 0.5f;
    float y0 = fmaxf(oy - diag * 0.5f, 0.0f);
    float x0 = fmaxf(ox - diag * 0.5f, 0.0f);
    y0 = (y0 + diag > (float)Him) ? ((float)Him - diag) : y0;
    x0 = (x0 + diag > (float)Wim) ? ((float)Wim - diag) : x0;
    float y0i   = floorf(y0);
    float x0i   = floorf(x0);
    float phi   = fmaxf(floorf(ps), 1.0f);
    float diagi = floorf(diag);

    Geo g;
    g.y0i = y0i; g.x0i = x0i; g.diagi = diagi; g.phi = phi;
    g.cc  = (diagi - 1.0f) * 0.5f;
    g.top = floorf((diagi - phi) * 0.5f);
    g.r   = 300.0f / phi;       // PH == PW == 300
    g.ca  = cosf(angle);
    g.sa  = sinf(angle);
    g.bright = bright;
    g.k2a = k20; g.k2b = k21;
    g.valid = (phi * phi > 60.0f) ? 1 : 0;
    g.pad = 0;
    g_geo[b][n] = g;
}

// ---------------------------------------------------------------------------
// K1: copy images -> img_out, zero mask_out, per-image partial sums (double)
// grid (32, 16), 256 threads
// ---------------------------------------------------------------------------
__global__ void k_copy(const float* __restrict__ images, float* __restrict__ out) {
    const size_t IMG = (size_t)Him * Wim * 3;       // 1,228,800
    int b = blockIdx.y, g = blockIdx.x;
    size_t base = (size_t)b * IMG + (size_t)g * (IMG / 32);
    const float4* src  = (const float4*)(images + base);
    float4* dimg = (float4*)(out + base);
    float4* dmsk = (float4*)(out + (size_t)Bimg * IMG + base);
    const int nvec = (int)((IMG / 32) / 4);         // 9600
    double acc = 0.0;
    float4 z = make_float4(0.f, 0.f, 0.f, 0.f);
    for (int i = threadIdx.x; i < nvec; i += blockDim.x) {
        float4 v = src[i];
        dimg[i] = v;
        dmsk[i] = z;
        acc += (double)v.x + (double)v.y + (double)v.z + (double)v.w;
    }
    __shared__ double sh[256];
    sh[threadIdx.x] = acc;
    __syncthreads();
    for (int s = 128; s > 0; s >>= 1) {
        if (threadIdx.x < s) sh[threadIdx.x] += sh[threadIdx.x + s];
        __syncthreads();
    }
    if (threadIdx.x == 0) g_isum[b][g] = sh[0];
}

// ---------------------------------------------------------------------------
// K2: per-image sum of clip(w*patch+b, -1, 1). grid (8, 16), 256 threads
// ---------------------------------------------------------------------------
__global__ void k_psum(const float* __restrict__ patch) {
    const int PTOT = PHp * PWp * 3;                 // 270,000
    int b = blockIdx.y, g = blockIdx.x;
    int chunk = PTOT / 8;                           // 33,750
    int base = g * chunk;
    float w0 = g_w[b][0], w1 = g_w[b][1], w2 = g_w[b][2];
    float b0 = g_bj[b][0], b1 = g_bj[b][1], b2 = g_bj[b][2];
    double acc = 0.0;
    for (int i = base + threadIdx.x; i < base + chunk; i += blockDim.x) {
        int c = i % 3;
        float wv = (c == 0) ? w0 : ((c == 1) ? w1 : w2);
        float bv = (c == 0) ? b0 : ((c == 1) ? b1 : b2);
        float v = fminf(fmaxf(wv * patch[i] + bv, -1.0f), 1.0f);
        acc += (double)v;
    }
    __shared__ double sh[256];
    sh[threadIdx.x] = acc;
    __syncthreads();
    for (int s = 128; s > 0; s >>= 1) {
        if (threadIdx.x < s) sh[threadIdx.x] += sh[threadIdx.x + s];
        __syncthreads();
    }
    if (threadIdx.x == 0) g_psum[b][g] = sh[0];
}

// ---------------------------------------------------------------------------
// K3: finalize brightness shift s[b] = mean(img) - mean(p)
// ---------------------------------------------------------------------------
__global__ void k_fin() {
    int b = threadIdx.x;
    if (b >= Bimg) return;
    double si = 0.0;
    for (int g = 0; g < 32; g++) si += g_isum[b][g];
    double sp = 0.0;
    for (int g = 0; g < 8; g++) sp += g_psum[b][g];
    float mi = (float)(si / 1228800.0);
    float mp = (float)(sp / 270000.0);
    g_s[b] = mi - mp;
}

// ---------------------------------------------------------------------------
// K4: one box-paste step (launched 16x, sequentially dependent)
// grid (40, 40, 16), block (16, 16)
// ---------------------------------------------------------------------------
__global__ void k_box(const float* __restrict__ images,
                      const float* __restrict__ patch,
                      float* __restrict__ oimg,
                      float* __restrict__ omask,
                      int n) {
    int b = blockIdx.z;
    Geo g = g_geo[b][n];
    if (!g.valid) return;
    int diag = (int)g.diagi;
    int ty = blockIdx.y * 16 + threadIdx.y;
    int tx = blockIdx.x * 16 + threadIdx.x;
    if (ty >= diag || tx >= diag) return;

    int y = (int)g.y0i + ty;
    int x = (int)g.x0i + tx;
    float u = (float)ty;                // exact: yy - y0i
    float v = (float)tx;
    float um = u - g.cc, vm = v - g.cc;
    float su = g.cc + g.ca * um - g.sa * vm;
    float sv = g.cc + g.sa * um + g.ca * vm;
    float py = su - g.top;
    float px = sv - g.top;
    float lim = g.phi - 1.0f;
    bool vsrc = (py >= 0.0f) && (py <= lim) && (px >= 0.0f) && (px <= lim);

    size_t base = (((size_t)b * Him + y) * Wim + x) * 3;
    float val0, val1, val2;

    if (vsrc) {
        float sy = (py + 0.5f) * g.r - 0.5f;
        float sx = (px + 0.5f) * g.r - 0.5f;
        float fy = floorf(sy), fx = floorf(sx);
        float wy = sy - fy,    wx = sx - fx;
        int y0c = min(max((int)fy, 0), PHp - 1);
        int y1c = min(y0c + 1, PHp - 1);
        int x0c = min(max((int)fx, 0), PWp - 1);
        int x1c = min(x0c + 1, PWp - 1);
        float s = g_s[b];
        float omy = 1.0f - wy, omx = 1.0f - wx;
        size_t o00 = ((size_t)y0c * PWp + x0c) * 3;
        size_t o01 = ((size_t)y0c * PWp + x1c) * 3;
        size_t o10 = ((size_t)y1c * PWp + x0c) * 3;
        size_t o11 = ((size_t)y1c * PWp + x1c) * 3;
        uint64_t nbase = (uint64_t)(((uint32_t)y * (uint32_t)Wim + (uint32_t)x) * 3u);
        float vals[3];
        #pragma unroll
        for (int c = 0; c < 3; c++) {
            float wc = g_w[b][c], bc = g_bj[b][c];
            float p00 = fminf(fmaxf(fminf(fmaxf(wc * patch[o00 + c] + bc, -1.0f), 1.0f) + s, -1.0f), 1.0f);
            float p01 = fminf(fmaxf(fminf(fmaxf(wc * patch[o01 + c] + bc, -1.0f), 1.0f) + s, -1.0f), 1.0f);
            float p10 = fminf(fmaxf(fminf(fmaxf(wc * patch[o10 + c] + bc, -1.0f), 1.0f) + s, -1.0f), 1.0f);
            float p11 = fminf(fmaxf(fminf(fmaxf(wc * patch[o11 + c] + bc, -1.0f), 1.0f) + s, -1.0f), 1.0f);
            float samp = p00 * omy * omx + p01 * omy * wx + p10 * wy * omx + p11 * wy * wx;
            uint32_t bits = rbits(g.k2a, g.k2b, nbase + (uint64_t)c);
            float noise = fmaxf(-0.1f, bits_to_unit(bits) * 0.2f - 0.1f);
            float im = fminf(fmaxf(samp + noise + g.bright, -1.0f), 1.0f);
            vals[c] = im;
        }
        oimg[base + 0] = vals[0];
        oimg[base + 1] = vals[1];
        oimg[base + 2] = vals[2];
        val0 = vals[0]; val1 = vals[1]; val2 = vals[2];
    } else {
        // val = current background; image unchanged (skip redundant store)
        val0 = oimg[base + 0];
        val1 = oimg[base + 1];
        val2 = oimg[base + 2];
    }

    omask[base + 0] = images[base + 0] - val0;
    omask[base + 1] = images[base + 1] - val1;
    omask[base + 2] = images[base + 2] - val2;
}

// ---------------------------------------------------------------------------
extern "C" void kernel_launch(void* const* d_in, const int* in_sizes, int n_in,
                              void* d_out, int out_size) {
    const float* boxes  = (const float*)d_in[0];
    const float* images = (const float*)d_in[1];
    const float* patch  = (const float*)d_in[2];
    const float* scale  = (const float*)d_in[3];
    float* out   = (float*)d_out;
    float* omask = out + (size_t)Bimg * Him * Wim * 3;

    k_setup<<<1, 256>>>(boxes, scale);
    k_copy<<<dim3(32, 16), 256>>>(images, out);
    k_psum<<<dim3(8, 16), 256>>>(patch);
    k_fin<<<1, 32>>>();

    dim3 bthr(16, 16);
    dim3 bgrid((Wim + 15) / 16, (Him + 15) / 16, Bimg);
    for (int n = 0; n < Nbox; n++) {
        k_box<<<bgrid, bthr>>>(images, patch, out, omask, n);
    }
    (void)in_sizes; (void)n_in; (void)out_size;
}

// round 2
// speedup vs baseline: 1.9813x; 1.9813x over previous
#include <cuda_runtime.h>
#include <stdint.h>
#include <math.h>

#define Bimg 16
#define Nbox 16
#define Him  640
#define Wim  640
#define PHp  300
#define PWp  300
#define PTOT (PHp*PWp*3)

// ---------------------------------------------------------------------------
// JAX threefry2x32 (20 rounds), partitionable random-bits convention
// ---------------------------------------------------------------------------
__device__ __forceinline__ void tf2x32(uint32_t k0, uint32_t k1,
                                       uint32_t x0, uint32_t x1,
                                       uint32_t& o0, uint32_t& o1) {
    uint32_t ks2 = k0 ^ k1 ^ 0x1BD11BDAu;
    x0 += k0; x1 += k1;
#define TF_RND(r) { x0 += x1; x1 = __funnelshift_l(x1, x1, (r)); x1 ^= x0; }
    TF_RND(13) TF_RND(15) TF_RND(26) TF_RND(6)
    x0 += k1;  x1 += ks2 + 1u;
    TF_RND(17) TF_RND(29) TF_RND(16) TF_RND(24)
    x0 += ks2; x1 += k0 + 2u;
    TF_RND(13) TF_RND(15) TF_RND(26) TF_RND(6)
    x0 += k0;  x1 += k1 + 3u;
    TF_RND(17) TF_RND(29) TF_RND(16) TF_RND(24)
    x0 += k1;  x1 += ks2 + 4u;
    TF_RND(13) TF_RND(15) TF_RND(26) TF_RND(6)
    x0 += ks2; x1 += k0 + 5u;
#undef TF_RND
    o0 = x0; o1 = x1;
}

__device__ __forceinline__ uint32_t rbits(uint32_t k0, uint32_t k1, uint64_t idx) {
    uint32_t a, b;
    tf2x32(k0, k1, (uint32_t)(idx >> 32), (uint32_t)idx, a, b);
    return a ^ b;
}

// 3 interleaved threefry chains, counters (c, c+1, c+2) with hi word = 0.
__device__ __forceinline__ void tf3(uint32_t k0, uint32_t k1, uint32_t c0,
                                    uint32_t out[3]) {
    uint32_t ks2 = k0 ^ k1 ^ 0x1BD11BDAu;
    uint32_t a0 = k0, a1 = k0, a2 = k0;                // x0_in == 0
    uint32_t b0 = c0 + k1, b1 = c0 + 1u + k1, b2 = c0 + 2u + k1;
#define R3(r)  { a0 += b0; b0 = __funnelshift_l(b0,b0,(r)); b0 ^= a0; \
                 a1 += b1; b1 = __funnelshift_l(b1,b1,(r)); b1 ^= a1; \
                 a2 += b2; b2 = __funnelshift_l(b2,b2,(r)); b2 ^= a2; }
#define INJ3(ka, kb) { a0 += (ka); b0 += (kb); a1 += (ka); b1 += (kb); a2 += (ka); b2 += (kb); }
    R3(13) R3(15) R3(26) R3(6)
    INJ3(k1, ks2 + 1u)
    R3(17) R3(29) R3(16) R3(24)
    INJ3(ks2, k0 + 2u)
    R3(13) R3(15) R3(26) R3(6)
    INJ3(k0, k1 + 3u)
    R3(17) R3(29) R3(16) R3(24)
    INJ3(k1, ks2 + 4u)
    R3(13) R3(15) R3(26) R3(6)
    out[0] = (a0 + ks2) ^ (b0 + k0 + 5u);
    out[1] = (a1 + ks2) ^ (b1 + k0 + 5u);
    out[2] = (a2 + ks2) ^ (b2 + k0 + 5u);
#undef R3
#undef INJ3
}

__device__ __forceinline__ float bits_to_unit(uint32_t bits) {
    return __uint_as_float((bits >> 9) | 0x3f800000u) - 1.0f;
}

__device__ __forceinline__ float juniform(uint32_t k0, uint32_t k1, uint64_t i,
                                          float lo, float hi) {
    float f = bits_to_unit(rbits(k0, k1, i));
    return fmaxf(lo, f * (hi - lo) + lo);
}

__device__ __forceinline__ float erfinv_xla(float x) {
    float w = -log1pf(-x * x);
    float p;
    if (w < 5.0f) {
        w -= 2.5f;
        p = 2.81022636e-08f;
        p = fmaf(p, w, 3.43273939e-07f);
        p = fmaf(p, w, -3.5233877e-06f);
        p = fmaf(p, w, -4.39150654e-06f);
        p = fmaf(p, w, 0.00021858087f);
        p = fmaf(p, w, -0.00125372503f);
        p = fmaf(p, w, -0.00417768164f);
        p = fmaf(p, w, 0.246640727f);
        p = fmaf(p, w, 1.50140941f);
    } else {
        w = sqrtf(w) - 3.0f;
        p = -0.000200214257f;
        p = fmaf(p, w, 0.000100950558f);
        p = fmaf(p, w, 0.00134934322f);
        p = fmaf(p, w, -0.00367342844f);
        p = fmaf(p, w, 0.00573950773f);
        p = fmaf(p, w, -0.0076224613f);
        p = fmaf(p, w, 0.00943887047f);
        p = fmaf(p, w, 1.00167406f);
        p = fmaf(p, w, 2.83297682f);
    }
    return p * x;
}

__device__ __forceinline__ float jnormal(uint32_t k0, uint32_t k1, uint64_t i) {
    const float lo = -0.99999994f;
    float u = juniform(k0, k1, i, lo, 1.0f);
    return 1.41421354f * erfinv_xla(u);
}

// ---------------------------------------------------------------------------
// Device scratch
// ---------------------------------------------------------------------------
struct Geo {
    float y0i, x0i, diagi, phi, cc, top, r, ca, sa, bright;
    uint32_t k2a, k2b;
    int valid;
    int pad;
};                                      // 14 words

__device__ Geo    g_geo[Bimg][Nbox];
__device__ float  g_w[Bimg][3];
__device__ float  g_bj[Bimg][3];
__device__ float  g_s[Bimg];
__device__ double g_isum[Bimg][32];
__device__ double g_psum[Bimg][8];
__device__ float  g_adjP[Bimg][PTOT];   // per-image pre-adjusted patch (17.3 MB)

// ---------------------------------------------------------------------------
// K0: key chains + geometry (1 block)
// ---------------------------------------------------------------------------
__global__ void k_setup(const float* __restrict__ boxes,
                        const float* __restrict__ scale_p) {
    int t = threadIdx.x;
    if (t >= Bimg * Nbox) return;
    int b = t >> 4;
    int n = t & 15;
    float scale = scale_p[0];

    uint32_t ib0, ib1;
    tf2x32(0u, 42u, 0u, (uint32_t)b, ib0, ib1);
    uint32_t kw0, kw1, kB0, kB1, kl0, kl1;
    tf2x32(ib0, ib1, 0u, 0u, kw0, kw1);
    tf2x32(ib0, ib1, 0u, 1u, kB0, kB1);
    tf2x32(ib0, ib1, 0u, 2u, kl0, kl1);

    if (n == 0) {
        #pragma unroll
        for (int c = 0; c < 3; c++) {
            g_w[b][c]  = jnormal(kw0, kw1, (uint64_t)c) * 0.1f + 0.5f;
            g_bj[b][c] = jnormal(kB0, kB1, (uint64_t)c) * 0.01f;
        }
    }

    uint32_t kn0, kn1;
    tf2x32(kl0, kl1, 0u, (uint32_t)n, kn0, kn1);
    uint32_t k10, k11, k20, k21, k30, k31;
    tf2x32(kn0, kn1, 0u, 0u, k10, k11);
    tf2x32(kn0, kn1, 0u, 1u, k20, k21);
    tf2x32(kn0, kn1, 0u, 2u, k30, k31);

    const float MAXA = (float)(20.0 * 3.14159265358979323846 / 180.0);
    float angle  = juniform(k10, k11, 0ull, -MAXA, MAXA);
    float bright = juniform(k30, k31, 0ull, -0.3f, 0.3f);

    const float* bx = boxes + ((size_t)b * Nbox + n) * 4;
    float ymin = bx[0], xmin = bx[1], ymax = bx[2], xmax = bx[3];
    float h  = ymax - ymin;
    float ww = xmax - xmin;
    float longer = fmaxf(h, ww);
    float ps   = floorf(longer * scale);
    float diag = fminf(sqrtf(2.0f) * ps, (float)Wim);
    float oy = ymin + h * 0.5f;
    float ox = xmin + ww * 0.5f;
    float y0 = fmaxf(oy - diag * 0.5f, 0.0f);
    float x0 = fmaxf(ox - diag * 0.5f, 0.0f);
    y0 = (y0 + diag > (float)Him) ? ((float)Him - diag) : y0;
    x0 = (x0 + diag > (float)Wim) ? ((float)Wim - diag) : x0;
    float y0i   = floorf(y0);
    float x0i   = floorf(x0);
    float phi   = fmaxf(floorf(ps), 1.0f);
    float diagi = floorf(diag);

    Geo g;
    g.y0i = y0i; g.x0i = x0i; g.diagi = diagi; g.phi = phi;
    g.cc  = (diagi - 1.0f) * 0.5f;
    g.top = floorf((diagi - phi) * 0.5f);
    g.r   = 300.0f / phi;
    g.ca  = cosf(angle);
    g.sa  = sinf(angle);
    g.bright = bright;
    g.k2a = k20; g.k2b = k21;
    g.valid = (phi * phi > 60.0f) ? 1 : 0;
    g.pad = 0;
    g_geo[b][n] = g;
}

// ---------------------------------------------------------------------------
// K1: per-image sums (image mean; clipped-patch mean). grid (40,16).
// blocks 0..31: image chunks. blocks 32..39: patch chunks (need g_w/g_bj).
// ---------------------------------------------------------------------------
__global__ void k_sums(const float* __restrict__ images,
                       const float* __restrict__ patch) {
    int b = blockIdx.y, g = blockIdx.x;
    double acc = 0.0;
    if (g < 32) {
        const size_t IMG = (size_t)Him * Wim * 3;
        size_t base = (size_t)b * IMG + (size_t)g * (IMG / 32);
        const float4* src = (const float4*)(images + base);
        const int nvec = (int)((IMG / 32) / 4);     // 9600
        for (int i = threadIdx.x; i < nvec; i += blockDim.x) {
            float4 v = src[i];
            acc += (double)v.x + (double)v.y + (double)v.z + (double)v.w;
        }
    } else {
        int gp = g - 32;
        int chunk = PTOT / 8;
        int base = gp * chunk;
        float w0 = g_w[b][0], w1 = g_w[b][1], w2 = g_w[b][2];
        float b0 = g_bj[b][0], b1 = g_bj[b][1], b2 = g_bj[b][2];
        for (int i = base + threadIdx.x; i < base + chunk; i += blockDim.x) {
            int c = i % 3;
            float wv = (c == 0) ? w0 : ((c == 1) ? w1 : w2);
            float bv = (c == 0) ? b0 : ((c == 1) ? b1 : b2);
            float v = fminf(fmaxf(wv * patch[i] + bv, -1.0f), 1.0f);
            acc += (double)v;
        }
    }
    __shared__ double sh[256];
    sh[threadIdx.x] = acc;
    __syncthreads();
    for (int s = 128; s > 0; s >>= 1) {
        if (threadIdx.x < s) sh[threadIdx.x] += sh[threadIdx.x + s];
        __syncthreads();
    }
    if (threadIdx.x == 0) {
        if (g < 32) g_isum[b][g] = sh[0];
        else        g_psum[b][g - 32] = sh[0];
    }
}

__global__ void k_fin() {
    int b = threadIdx.x;
    if (b >= Bimg) return;
    double si = 0.0;
    for (int g = 0; g < 32; g++) si += g_isum[b][g];
    double sp = 0.0;
    for (int g = 0; g < 8; g++) sp += g_psum[b][g];
    g_s[b] = (float)(si / 1228800.0) - (float)(sp / 270000.0);
}

// ---------------------------------------------------------------------------
// K2: pre-adjust patch per image: clip(clip(w*patch+b) + s)
// grid ((PTOT+1023)/1024, 16), 256 thr, 4 elems/thread
// ---------------------------------------------------------------------------
__global__ void k_adj(const float* __restrict__ patch) {
    int b = blockIdx.y;
    float s = g_s[b];
    float w0 = g_w[b][0], w1 = g_w[b][1], w2 = g_w[b][2];
    float b0 = g_bj[b][0], b1 = g_bj[b][1], b2 = g_bj[b][2];
    int i0 = (blockIdx.x * 256 + threadIdx.x) * 4;
    #pragma unroll
    for (int k = 0; k < 4; k++) {
        int i = i0 + k;
        if (i >= PTOT) break;
        int c = i % 3;
        float wv = (c == 0) ? w0 : ((c == 1) ? w1 : w2);
        float bv = (c == 0) ? b0 : ((c == 1) ? b1 : b2);
        float v = fminf(fmaxf(wv * patch[i] + bv, -1.0f), 1.0f);
        v = fminf(fmaxf(v + s, -1.0f), 1.0f);
        g_adjP[b][i] = v;
    }
}

// ---------------------------------------------------------------------------
// K3: per-pixel last-writer resolve over all 16 boxes, single launch.
// grid (20, 80, 16), block (32, 8): 32x8 pixel tiles.
// ---------------------------------------------------------------------------
__global__ void k_main(const float* __restrict__ images,
                       float* __restrict__ oimg,
                       float* __restrict__ omask) {
    __shared__ Geo sg[Nbox];
    int b = blockIdx.z;
    int t = threadIdx.y * 32 + threadIdx.x;
    if (t < Nbox * 14)
        ((float*)sg)[t] = ((const float*)&g_geo[b][0])[t];
    __syncthreads();

    int x = blockIdx.x * 32 + threadIdx.x;
    int y = blockIdx.y * 8 + threadIdx.y;
    float tx0 = (float)(blockIdx.x * 32);
    float ty0 = (float)(blockIdx.y * 8);

    // block-uniform candidate mask
    unsigned m = 0;
    #pragma unroll
    for (int n = 0; n < Nbox; n++) {
        const Geo& G = sg[n];
        bool ov = G.valid &&
                  (ty0 + 8.0f > G.y0i) && (ty0 < G.y0i + G.diagi) &&
                  (tx0 + 32.0f > G.x0i) && (tx0 < G.x0i + G.diagi);
        if (ov) m |= (1u << n);
    }

    size_t base = (((size_t)b * Him + y) * Wim + x) * 3;
    float o0 = images[base], o1 = images[base + 1], o2 = images[base + 2];

    if (m == 0) {
        oimg[base] = o0; oimg[base + 1] = o1; oimg[base + 2] = o2;
        omask[base] = 0.f; omask[base + 1] = 0.f; omask[base + 2] = 0.f;
        return;
    }

    int V = -1;
    float vpy = 0.f, vpx = 0.f, vr = 0.f, vbr = 0.f;
    uint32_t vk0 = 0, vk1 = 0;
    float fy_ = (float)y, fx_ = (float)x;

    while (m) {
        int n = __ffs(m) - 1;
        m &= m - 1;
        const Geo& G = sg[n];
        float u = fy_ - G.y0i;
        float v = fx_ - G.x0i;
        if (u >= 0.f && v >= 0.f && u < G.diagi && v < G.diagi) {
            float um = u - G.cc, vm = v - G.cc;
            float py = G.cc + G.ca * um - G.sa * vm - G.top;
            float px = G.cc + G.sa * um + G.ca * vm - G.top;
            float lim = G.phi - 1.0f;
            if (py >= 0.f && py <= lim && px >= 0.f && px <= lim) {
                V = n; vpy = py; vpx = px;
                vr = G.r; vbr = G.bright; vk0 = G.k2a; vk1 = G.k2b;
            }
        }
    }

    float r0 = o0, r1 = o1, r2 = o2;
    float m0 = 0.f, m1 = 0.f, m2 = 0.f;

    if (V >= 0) {
        float sy = (vpy + 0.5f) * vr - 0.5f;
        float sx = (vpx + 0.5f) * vr - 0.5f;
        float fy = floorf(sy), fx = floorf(sx);
        float wy = sy - fy, wx = sx - fx;
        int y0c = min(max((int)fy, 0), PHp - 1);
        int y1c = min(y0c + 1, PHp - 1);
        int x0c = min(max((int)fx, 0), PWp - 1);
        int x1c = min(x0c + 1, PWp - 1);
        const float* P = g_adjP[b];
        int o00 = (y0c * PWp + x0c) * 3;
        int o01 = (y0c * PWp + x1c) * 3;
        int o10 = (y1c * PWp + x0c) * 3;
        int o11 = (y1c * PWp + x1c) * 3;

        uint32_t nb = ((uint32_t)y * (uint32_t)Wim + (uint32_t)x) * 3u;
        uint32_t bits[3];
        tf3(vk0, vk1, nb, bits);

        float omy = 1.0f - wy, omx = 1.0f - wx;
        float w00 = omy * omx, w01 = omy * wx, w10 = wy * omx, w11 = wy * wx;
        float res[3];
        #pragma unroll
        for (int c = 0; c < 3; c++) {
            float p00 = P[o00 + c], p01 = P[o01 + c];
            float p10 = P[o10 + c], p11 = P[o11 + c];
            float samp = p00 * w00 + p01 * w01 + p10 * w10 + p11 * w11;
            float noise = fmaxf(-0.1f, fmaf(bits_to_unit(bits[c]), 0.2f, -0.1f));
            res[c] = fminf(fmaxf(samp + noise + vbr, -1.0f), 1.0f);
        }
        r0 = res[0]; r1 = res[1]; r2 = res[2];
        m0 = o0 - r0; m1 = o1 - r1; m2 = o2 - r2;
    }

    oimg[base] = r0; oimg[base + 1] = r1; oimg[base + 2] = r2;
    omask[base] = m0; omask[base + 1] = m1; omask[base + 2] = m2;
}

// ---------------------------------------------------------------------------
extern "C" void kernel_launch(void* const* d_in, const int* in_sizes, int n_in,
                              void* d_out, int out_size) {
    const float* boxes  = (const float*)d_in[0];
    const float* images = (const float*)d_in[1];
    const float* patch  = (const float*)d_in[2];
    const float* scale  = (const float*)d_in[3];
    float* out   = (float*)d_out;
    float* omask = out + (size_t)Bimg * Him * Wim * 3;

    k_setup<<<1, 256>>>(boxes, scale);
    k_sums<<<dim3(40, 16), 256>>>(images, patch);
    k_fin<<<1, 32>>>();
    k_adj<<<dim3((PTOT + 1023) / 1024, 16), 256>>>(patch);
    k_main<<<dim3(20, 80, 16), dim3(32, 8)>>>(images, out, omask);

    (void)in_sizes; (void)n_in; (void)out_size;
}

// round 3
// speedup vs baseline: 2.0040x; 1.0115x over previous
#include <cuda_runtime.h>
#include <stdint.h>
#include <math.h>

#define Bimg 16
#define Nbox 16
#define Him  640
#define Wim  640
#define PHp  300
#define PWp  300
#define PTOT (PHp*PWp*3)

// ---------------------------------------------------------------------------
// JAX threefry2x32 (20 rounds), partitionable random-bits convention
// ---------------------------------------------------------------------------
__device__ __forceinline__ void tf2x32(uint32_t k0, uint32_t k1,
                                       uint32_t x0, uint32_t x1,
                                       uint32_t& o0, uint32_t& o1) {
    uint32_t ks2 = k0 ^ k1 ^ 0x1BD11BDAu;
    x0 += k0; x1 += k1;
#define TF_RND(r) { x0 += x1; x1 = __funnelshift_l(x1, x1, (r)); x1 ^= x0; }
    TF_RND(13) TF_RND(15) TF_RND(26) TF_RND(6)
    x0 += k1;  x1 += ks2 + 1u;
    TF_RND(17) TF_RND(29) TF_RND(16) TF_RND(24)
    x0 += ks2; x1 += k0 + 2u;
    TF_RND(13) TF_RND(15) TF_RND(26) TF_RND(6)
    x0 += k0;  x1 += k1 + 3u;
    TF_RND(17) TF_RND(29) TF_RND(16) TF_RND(24)
    x0 += k1;  x1 += ks2 + 4u;
    TF_RND(13) TF_RND(15) TF_RND(26) TF_RND(6)
    x0 += ks2; x1 += k0 + 5u;
#undef TF_RND
    o0 = x0; o1 = x1;
}

__device__ __forceinline__ uint32_t rbits(uint32_t k0, uint32_t k1, uint64_t idx) {
    uint32_t a, b;
    tf2x32(k0, k1, (uint32_t)(idx >> 32), (uint32_t)idx, a, b);
    return a ^ b;
}

// 3 interleaved threefry chains, counters (c0, c0+1, c0+2), hi word = 0.
__device__ __forceinline__ void tf3(uint32_t k0, uint32_t k1, uint32_t c0,
                                    uint32_t out[3]) {
    uint32_t ks2 = k0 ^ k1 ^ 0x1BD11BDAu;
    uint32_t a0 = k0, a1 = k0, a2 = k0;
    uint32_t b0 = c0 + k1, b1 = c0 + 1u + k1, b2 = c0 + 2u + k1;
#define R3(r)  { a0 += b0; b0 = __funnelshift_l(b0,b0,(r)); b0 ^= a0; \
                 a1 += b1; b1 = __funnelshift_l(b1,b1,(r)); b1 ^= a1; \
                 a2 += b2; b2 = __funnelshift_l(b2,b2,(r)); b2 ^= a2; }
#define INJ3(ka, kb) { a0 += (ka); b0 += (kb); a1 += (ka); b1 += (kb); a2 += (ka); b2 += (kb); }
    R3(13) R3(15) R3(26) R3(6)
    INJ3(k1, ks2 + 1u)
    R3(17) R3(29) R3(16) R3(24)
    INJ3(ks2, k0 + 2u)
    R3(13) R3(15) R3(26) R3(6)
    INJ3(k0, k1 + 3u)
    R3(17) R3(29) R3(16) R3(24)
    INJ3(k1, ks2 + 4u)
    R3(13) R3(15) R3(26) R3(6)
    out[0] = (a0 + ks2) ^ (b0 + k0 + 5u);
    out[1] = (a1 + ks2) ^ (b1 + k0 + 5u);
    out[2] = (a2 + ks2) ^ (b2 + k0 + 5u);
#undef R3
#undef INJ3
}

__device__ __forceinline__ float bits_to_unit(uint32_t bits) {
    return __uint_as_float((bits >> 9) | 0x3f800000u) - 1.0f;
}

__device__ __forceinline__ float juniform(uint32_t k0, uint32_t k1, uint64_t i,
                                          float lo, float hi) {
    float f = bits_to_unit(rbits(k0, k1, i));
    return fmaxf(lo, f * (hi - lo) + lo);
}

__device__ __forceinline__ float erfinv_xla(float x) {
    float w = -log1pf(-x * x);
    float p;
    if (w < 5.0f) {
        w -= 2.5f;
        p = 2.81022636e-08f;
        p = fmaf(p, w, 3.43273939e-07f);
        p = fmaf(p, w, -3.5233877e-06f);
        p = fmaf(p, w, -4.39150654e-06f);
        p = fmaf(p, w, 0.00021858087f);
        p = fmaf(p, w, -0.00125372503f);
        p = fmaf(p, w, -0.00417768164f);
        p = fmaf(p, w, 0.246640727f);
        p = fmaf(p, w, 1.50140941f);
    } else {
        w = sqrtf(w) - 3.0f;
        p = -0.000200214257f;
        p = fmaf(p, w, 0.000100950558f);
        p = fmaf(p, w, 0.00134934322f);
        p = fmaf(p, w, -0.00367342844f);
        p = fmaf(p, w, 0.00573950773f);
        p = fmaf(p, w, -0.0076224613f);
        p = fmaf(p, w, 0.00943887047f);
        p = fmaf(p, w, 1.00167406f);
        p = fmaf(p, w, 2.83297682f);
    }
    return p * x;
}

__device__ __forceinline__ float jnormal(uint32_t k0, uint32_t k1, uint64_t i) {
    const float lo = -0.99999994f;
    float u = juniform(k0, k1, i, lo, 1.0f);
    return 1.41421354f * erfinv_xla(u);
}

// w,b jitter scalars for image b (deterministic key chain)
__device__ __forceinline__ void wb_for(int b, float w[3], float bb[3]) {
    uint32_t ib0, ib1;
    tf2x32(0u, 42u, 0u, (uint32_t)b, ib0, ib1);
    uint32_t kw0, kw1, kB0, kB1;
    tf2x32(ib0, ib1, 0u, 0u, kw0, kw1);
    tf2x32(ib0, ib1, 0u, 1u, kB0, kB1);
    #pragma unroll
    for (int c = 0; c < 3; c++) {
        w[c]  = jnormal(kw0, kw1, (uint64_t)c) * 0.1f + 0.5f;
        bb[c] = jnormal(kB0, kB1, (uint64_t)c) * 0.01f;
    }
}

// ---------------------------------------------------------------------------
// Device scratch
// ---------------------------------------------------------------------------
struct Geo {
    float y0i, x0i, diagi, phi, cc, top, r, ca, sa, bright;
    uint32_t k2a, k2b;
    int valid;
    int pad;
};                                      // 14 words = 56 B

__device__ Geo    g_geo[Bimg][Nbox];
__device__ float  g_w[Bimg][3];
__device__ float  g_bj[Bimg][3];
__device__ double g_isum[Bimg][32];
__device__ double g_psum[Bimg][8];
__device__ __align__(16) float g_adjP[Bimg][PTOT];

// ---------------------------------------------------------------------------
// K1: fused setup + sums. grid (41, 16), 256 thr.
//   x <  32 : image partial sums
//   x 32..39: clipped-patch partial sums (w,b computed inline)
//   x == 40 : per-box geometry + g_w/g_bj
// ---------------------------------------------------------------------------
__global__ void k_sums(const float* __restrict__ images,
                       const float* __restrict__ patch,
                       const float* __restrict__ boxes,
                       const float* __restrict__ scale_p) {
    int b = blockIdx.y, g = blockIdx.x;

    if (g == 40) {
        int n = threadIdx.x;
        if (n == 0) {
            float w[3], bb[3];
            wb_for(b, w, bb);
            #pragma unroll
            for (int c = 0; c < 3; c++) { g_w[b][c] = w[c]; g_bj[b][c] = bb[c]; }
        }
        if (n < Nbox) {
            float scale = scale_p[0];
            uint32_t ib0, ib1, kl0, kl1;
            tf2x32(0u, 42u, 0u, (uint32_t)b, ib0, ib1);
            tf2x32(ib0, ib1, 0u, 2u, kl0, kl1);
            uint32_t kn0, kn1;
            tf2x32(kl0, kl1, 0u, (uint32_t)n, kn0, kn1);
            uint32_t k10, k11, k20, k21, k30, k31;
            tf2x32(kn0, kn1, 0u, 0u, k10, k11);
            tf2x32(kn0, kn1, 0u, 1u, k20, k21);
            tf2x32(kn0, kn1, 0u, 2u, k30, k31);

            const float MAXA = (float)(20.0 * 3.14159265358979323846 / 180.0);
            float angle  = juniform(k10, k11, 0ull, -MAXA, MAXA);
            float bright = juniform(k30, k31, 0ull, -0.3f, 0.3f);

            const float* bx = boxes + ((size_t)b * Nbox + n) * 4;
            float ymin = bx[0], xmin = bx[1], ymax = bx[2], xmax = bx[3];
            float h  = ymax - ymin;
            float ww = xmax - xmin;
            float longer = fmaxf(h, ww);
            float ps   = floorf(longer * scale);
            float diag = fminf(sqrtf(2.0f) * ps, (float)Wim);
            float oy = ymin + h * 0.5f;
            float ox = xmin + ww * 0.5f;
            float y0 = fmaxf(oy - diag * 0.5f, 0.0f);
            float x0 = fmaxf(ox - diag * 0.5f, 0.0f);
            y0 = (y0 + diag > (float)Him) ? ((float)Him - diag) : y0;
            x0 = (x0 + diag > (float)Wim) ? ((float)Wim - diag) : x0;
            float phi   = fmaxf(floorf(ps), 1.0f);
            float diagi = floorf(diag);

            Geo gg;
            gg.y0i = floorf(y0); gg.x0i = floorf(x0);
            gg.diagi = diagi; gg.phi = phi;
            gg.cc  = (diagi - 1.0f) * 0.5f;
            gg.top = floorf((diagi - phi) * 0.5f);
            gg.r   = 300.0f / phi;
            gg.ca  = cosf(angle);
            gg.sa  = sinf(angle);
            gg.bright = bright;
            gg.k2a = k20; gg.k2b = k21;
            gg.valid = (phi * phi > 60.0f) ? 1 : 0;
            gg.pad = 0;
            g_geo[b][n] = gg;
        }
        return;
    }

    double acc = 0.0;
    if (g < 32) {
        const size_t IMG = (size_t)Him * Wim * 3;
        size_t base = (size_t)b * IMG + (size_t)g * (IMG / 32);
        const float4* src = (const float4*)(images + base);
        const int nvec = (int)((IMG / 32) / 4);     // 9600
        for (int i = threadIdx.x; i < nvec; i += blockDim.x) {
            float4 v = src[i];
            acc += (double)v.x + (double)v.y + (double)v.z + (double)v.w;
        }
    } else {
        float w[3], bb[3];
        wb_for(b, w, bb);
        int gp = g - 32;
        int chunk = PTOT / 8;                        // 33750
        int base = gp * chunk;
        for (int i = base + threadIdx.x; i < base + chunk; i += blockDim.x) {
            int c = i % 3;
            float v = fminf(fmaxf(w[c] * patch[i] + bb[c], -1.0f), 1.0f);
            acc += (double)v;
        }
    }
    __shared__ double sh[256];
    sh[threadIdx.x] = acc;
    __syncthreads();
    for (int s = 128; s > 0; s >>= 1) {
        if (threadIdx.x < s) sh[threadIdx.x] += sh[threadIdx.x + s];
        __syncthreads();
    }
    if (threadIdx.x == 0) {
        if (g < 32) g_isum[b][g] = sh[0];
        else        g_psum[b][g - 32] = sh[0];
    }
}

// ---------------------------------------------------------------------------
// K2: pre-adjust patch per image: clip(clip(w*p+b) + s). Inline s-finalize.
// grid (88, 16), 256 thr; 12 floats (4 px) per thread, float4 I/O.
// ---------------------------------------------------------------------------
__global__ void k_adj(const float* __restrict__ patch) {
    int b = blockIdx.y;
    __shared__ float ss;
    if (threadIdx.x == 0) {
        double si = 0.0;
        #pragma unroll
        for (int g = 0; g < 32; g++) si += g_isum[b][g];
        double sp = 0.0;
        #pragma unroll
        for (int g = 0; g < 8; g++) sp += g_psum[b][g];
        ss = (float)(si / 1228800.0) - (float)(sp / 270000.0);
    }
    __syncthreads();
    float s = ss;
    float w0 = g_w[b][0], w1 = g_w[b][1], w2 = g_w[b][2];
    float b0 = g_bj[b][0], b1 = g_bj[b][1], b2 = g_bj[b][2];

    int i0 = (blockIdx.x * 256 + threadIdx.x) * 12;
    if (i0 >= PTOT) return;
    const float4* src = (const float4*)(patch + i0);
    float4* dst = (float4*)(&g_adjP[b][i0]);
    float4 v0 = src[0], v1 = src[1], v2 = src[2];

#define ADJ(x, wv, bv) fminf(fmaxf(fminf(fmaxf((wv)*(x)+(bv), -1.f), 1.f) + s, -1.f), 1.f)
    float4 r0, r1, r2;
    r0.x = ADJ(v0.x, w0, b0); r0.y = ADJ(v0.y, w1, b1);
    r0.z = ADJ(v0.z, w2, b2); r0.w = ADJ(v0.w, w0, b0);
    r1.x = ADJ(v1.x, w1, b1); r1.y = ADJ(v1.y, w2, b2);
    r1.z = ADJ(v1.z, w0, b0); r1.w = ADJ(v1.w, w1, b1);
    r2.x = ADJ(v2.x, w2, b2); r2.y = ADJ(v2.y, w0, b0);
    r2.z = ADJ(v2.z, w1, b1); r2.w = ADJ(v2.w, w2, b2);
#undef ADJ
    dst[0] = r0; dst[1] = r1; dst[2] = r2;
}

// ---------------------------------------------------------------------------
// K3: per-pixel last-writer resolve + compacted heavy phase.
// grid (20, 80, 16), block (32, 8).
// ---------------------------------------------------------------------------
__global__ void k_main(const float* __restrict__ images,
                       float* __restrict__ oimg,
                       float* __restrict__ omask) {
    __shared__ Geo   sg[Nbox];
    __shared__ float spy[256], spx[256];
    __shared__ float so0[256], so1[256], so2[256];
    __shared__ int   spk[256];
    __shared__ int   scnt;

    int b = blockIdx.z;
    int t = threadIdx.y * 32 + threadIdx.x;
    if (t < Nbox * 14)
        ((float*)sg)[t] = ((const float*)&g_geo[b][0])[t];
    if (t == 0) scnt = 0;
    __syncthreads();

    int x = blockIdx.x * 32 + threadIdx.x;
    int y = blockIdx.y * 8 + threadIdx.y;
    float tx0 = (float)(blockIdx.x * 32);
    float ty0 = (float)(blockIdx.y * 8);

    unsigned m = 0;
    #pragma unroll
    for (int n = 0; n < Nbox; n++) {
        const Geo& G = sg[n];
        bool ov = G.valid &&
                  (ty0 + 8.0f > G.y0i) && (ty0 < G.y0i + G.diagi) &&
                  (tx0 + 32.0f > G.x0i) && (tx0 < G.x0i + G.diagi);
        if (ov) m |= (1u << n);
    }

    size_t base = (((size_t)b * Him + y) * Wim + x) * 3;
    float o0 = images[base], o1 = images[base + 1], o2 = images[base + 2];

    if (m == 0) {   // block-uniform: no box touches this tile
        oimg[base] = o0; oimg[base + 1] = o1; oimg[base + 2] = o2;
        omask[base] = 0.f; omask[base + 1] = 0.f; omask[base + 2] = 0.f;
        return;
    }

    // ---- phase 1: resolve last-writer box per pixel ----
    int V = -1;
    float vpy = 0.f, vpx = 0.f;
    float fy_ = (float)y, fx_ = (float)x;
    while (m) {
        int n = __ffs(m) - 1;
        m &= m - 1;
        const Geo& G = sg[n];
        float u = fy_ - G.y0i;
        float v = fx_ - G.x0i;
        if (u >= 0.f && v >= 0.f && u < G.diagi && v < G.diagi) {
            float um = u - G.cc, vm = v - G.cc;
            float py = G.cc + G.ca * um - G.sa * vm - G.top;
            float px = G.cc + G.sa * um + G.ca * vm - G.top;
            float lim = G.phi - 1.0f;
            if (py >= 0.f && py <= lim && px >= 0.f && px <= lim) {
                V = n; vpy = py; vpx = px;
            }
        }
    }

    bool heavy = (V >= 0);
    if (!heavy) {
        oimg[base] = o0; oimg[base + 1] = o1; oimg[base + 2] = o2;
        omask[base] = 0.f; omask[base + 1] = 0.f; omask[base + 2] = 0.f;
    } else {
        so0[t] = o0; so1[t] = o1; so2[t] = o2;
    }

    // warp-aggregated enqueue
    unsigned wm = __ballot_sync(0xffffffffu, heavy);
    int lane = threadIdx.x;
    int wbase = 0;
    if (wm) {
        if (lane == 0) wbase = atomicAdd(&scnt, __popc(wm));
        wbase = __shfl_sync(0xffffffffu, wbase, 0);
        if (heavy) {
            int pos = wbase + __popc(wm & ((1u << lane) - 1u));
            spy[pos] = vpy; spx[pos] = vpx;
            spk[pos] = (t << 4) | V;
        }
    }
    __syncthreads();

    // ---- phase 2: dense processing of compacted heavy pixels ----
    int cnt = scnt;
    if (t < cnt) {
        int pk = spk[t];
        int p  = pk >> 4;
        const Geo& G = sg[pk & 15];
        float py = spy[t], px = spx[t];
        int yy = blockIdx.y * 8 + (p >> 5);
        int xx = blockIdx.x * 32 + (p & 31);

        float sy = (py + 0.5f) * G.r - 0.5f;
        float sx = (px + 0.5f) * G.r - 0.5f;
        float fy = floorf(sy), fx = floorf(sx);
        float wy = sy - fy, wx = sx - fx;
        int y0c = min(max((int)fy, 0), PHp - 1);
        int y1c = min(y0c + 1, PHp - 1);
        int x0c = min(max((int)fx, 0), PWp - 1);
        int x1c = min(x0c + 1, PWp - 1);
        const float* P = g_adjP[b];
        int o00 = (y0c * PWp + x0c) * 3;
        int o01 = (y0c * PWp + x1c) * 3;
        int o10 = (y1c * PWp + x0c) * 3;
        int o11 = (y1c * PWp + x1c) * 3;

        uint32_t nb = ((uint32_t)yy * (uint32_t)Wim + (uint32_t)xx) * 3u;
        uint32_t bits[3];
        tf3(G.k2a, G.k2b, nb, bits);

        float omy = 1.0f - wy, omx = 1.0f - wx;
        float w00 = omy * omx, w01 = omy * wx, w10 = wy * omx, w11 = wy * wx;
        float res[3];
        #pragma unroll
        for (int c = 0; c < 3; c++) {
            float samp = P[o00 + c] * w00 + P[o01 + c] * w01
                       + P[o10 + c] * w10 + P[o11 + c] * w11;
            float noise = fmaxf(-0.1f, fmaf(bits_to_unit(bits[c]), 0.2f, -0.1f));
            res[c] = fminf(fmaxf(samp + noise + G.bright, -1.0f), 1.0f);
        }

        size_t hb = (((size_t)b * Him + yy) * Wim + xx) * 3;
        oimg[hb]     = res[0]; oimg[hb + 1]  = res[1]; oimg[hb + 2]  = res[2];
        omask[hb]    = so0[p] - res[0];
        omask[hb + 1] = so1[p] - res[1];
        omask[hb + 2] = so2[p] - res[2];
    }
}

// ---------------------------------------------------------------------------
extern "C" void kernel_launch(void* const* d_in, const int* in_sizes, int n_in,
                              void* d_out, int out_size) {
    const float* boxes  = (const float*)d_in[0];
    const float* images = (const float*)d_in[1];
    const float* patch  = (const float*)d_in[2];
    const float* scale  = (const float*)d_in[3];
    float* out   = (float*)d_out;
    float* omask = out + (size_t)Bimg * Him * Wim * 3;

    k_sums<<<dim3(41, 16), 256>>>(images, patch, boxes, scale);
    k_adj<<<dim3(88, 16), 256>>>(patch);
    k_main<<<dim3(20, 80, 16), dim3(32, 8)>>>(images, out, omask);

    (void)in_sizes; (void)n_in; (void)out_size;
}

// round 4
// speedup vs baseline: 3.5021x; 1.7475x over previous
#include <cuda_runtime.h>
#include <stdint.h>
#include <math.h>

#define Bimg 16
#define Nbox 16
#define Him  640
#define Wim  640
#define PHp  300
#define PWp  300
#define PTOT (PHp*PWp*3)

// ---------------------------------------------------------------------------
// JAX threefry2x32 (20 rounds), partitionable random-bits convention
// ---------------------------------------------------------------------------
__device__ __forceinline__ void tf2x32(uint32_t k0, uint32_t k1,
                                       uint32_t x0, uint32_t x1,
                                       uint32_t& o0, uint32_t& o1) {
    uint32_t ks2 = k0 ^ k1 ^ 0x1BD11BDAu;
    x0 += k0; x1 += k1;
#define TF_RND(r) { x0 += x1; x1 = __funnelshift_l(x1, x1, (r)); x1 ^= x0; }
    TF_RND(13) TF_RND(15) TF_RND(26) TF_RND(6)
    x0 += k1;  x1 += ks2 + 1u;
    TF_RND(17) TF_RND(29) TF_RND(16) TF_RND(24)
    x0 += ks2; x1 += k0 + 2u;
    TF_RND(13) TF_RND(15) TF_RND(26) TF_RND(6)
    x0 += k0;  x1 += k1 + 3u;
    TF_RND(17) TF_RND(29) TF_RND(16) TF_RND(24)
    x0 += k1;  x1 += ks2 + 4u;
    TF_RND(13) TF_RND(15) TF_RND(26) TF_RND(6)
    x0 += ks2; x1 += k0 + 5u;
#undef TF_RND
    o0 = x0; o1 = x1;
}

__device__ __forceinline__ uint32_t rbits(uint32_t k0, uint32_t k1, uint64_t idx) {
    uint32_t a, b;
    tf2x32(k0, k1, (uint32_t)(idx >> 32), (uint32_t)idx, a, b);
    return a ^ b;
}

// 3 interleaved threefry chains, counters (c0, c0+1, c0+2), hi word = 0.
__device__ __forceinline__ void tf3(uint32_t k0, uint32_t k1, uint32_t c0,
                                    uint32_t out[3]) {
    uint32_t ks2 = k0 ^ k1 ^ 0x1BD11BDAu;
    uint32_t a0 = k0, a1 = k0, a2 = k0;
    uint32_t b0 = c0 + k1, b1 = c0 + 1u + k1, b2 = c0 + 2u + k1;
#define R3(r)  { a0 += b0; b0 = __funnelshift_l(b0,b0,(r)); b0 ^= a0; \
                 a1 += b1; b1 = __funnelshift_l(b1,b1,(r)); b1 ^= a1; \
                 a2 += b2; b2 = __funnelshift_l(b2,b2,(r)); b2 ^= a2; }
#define INJ3(ka, kb) { a0 += (ka); b0 += (kb); a1 += (ka); b1 += (kb); a2 += (ka); b2 += (kb); }
    R3(13) R3(15) R3(26) R3(6)
    INJ3(k1, ks2 + 1u)
    R3(17) R3(29) R3(16) R3(24)
    INJ3(ks2, k0 + 2u)
    R3(13) R3(15) R3(26) R3(6)
    INJ3(k0, k1 + 3u)
    R3(17) R3(29) R3(16) R3(24)
    INJ3(k1, ks2 + 4u)
    R3(13) R3(15) R3(26) R3(6)
    out[0] = (a0 + ks2) ^ (b0 + k0 + 5u);
    out[1] = (a1 + ks2) ^ (b1 + k0 + 5u);
    out[2] = (a2 + ks2) ^ (b2 + k0 + 5u);
#undef R3
#undef INJ3
}

__device__ __forceinline__ float bits_to_unit(uint32_t bits) {
    return __uint_as_float((bits >> 9) | 0x3f800000u) - 1.0f;
}

__device__ __forceinline__ float juniform(uint32_t k0, uint32_t k1, uint64_t i,
                                          float lo, float hi) {
    float f = bits_to_unit(rbits(k0, k1, i));
    return fmaxf(lo, f * (hi - lo) + lo);
}

__device__ __forceinline__ float erfinv_xla(float x) {
    float w = -log1pf(-x * x);
    float p;
    if (w < 5.0f) {
        w -= 2.5f;
        p = 2.81022636e-08f;
        p = fmaf(p, w, 3.43273939e-07f);
        p = fmaf(p, w, -3.5233877e-06f);
        p = fmaf(p, w, -4.39150654e-06f);
        p = fmaf(p, w, 0.00021858087f);
        p = fmaf(p, w, -0.00125372503f);
        p = fmaf(p, w, -0.00417768164f);
        p = fmaf(p, w, 0.246640727f);
        p = fmaf(p, w, 1.50140941f);
    } else {
        w = sqrtf(w) - 3.0f;
        p = -0.000200214257f;
        p = fmaf(p, w, 0.000100950558f);
        p = fmaf(p, w, 0.00134934322f);
        p = fmaf(p, w, -0.00367342844f);
        p = fmaf(p, w, 0.00573950773f);
        p = fmaf(p, w, -0.0076224613f);
        p = fmaf(p, w, 0.00943887047f);
        p = fmaf(p, w, 1.00167406f);
        p = fmaf(p, w, 2.83297682f);
    }
    return p * x;
}

__device__ __forceinline__ float jnormal(uint32_t k0, uint32_t k1, uint64_t i) {
    const float lo = -0.99999994f;
    float u = juniform(k0, k1, i, lo, 1.0f);
    return 1.41421354f * erfinv_xla(u);
}

// w,b jitter scalars for image b (deterministic key chain)
__device__ __forceinline__ void wb_for(int b, float w[3], float bb[3]) {
    uint32_t ib0, ib1;
    tf2x32(0u, 42u, 0u, (uint32_t)b, ib0, ib1);
    uint32_t kw0, kw1, kB0, kB1;
    tf2x32(ib0, ib1, 0u, 0u, kw0, kw1);
    tf2x32(ib0, ib1, 0u, 1u, kB0, kB1);
    #pragma unroll
    for (int c = 0; c < 3; c++) {
        w[c]  = jnormal(kw0, kw1, (uint64_t)c) * 0.1f + 0.5f;
        bb[c] = jnormal(kB0, kB1, (uint64_t)c) * 0.01f;
    }
}

// ---------------------------------------------------------------------------
// Device scratch
// ---------------------------------------------------------------------------
struct Geo {
    float y0i, x0i, diagi, phi, cc, top, r, ca, sa, bright;
    uint32_t k2a, k2b;
    int valid;
    int pad;
};                                      // 14 words = 56 B

__device__ Geo   g_geo[Bimg][Nbox];
__device__ float g_w[Bimg][3];
__device__ float g_bj[Bimg][3];
__device__ float g_isum[Bimg][32];
__device__ float g_psum[Bimg][8];
__device__ __align__(16) float g_adjP[Bimg][PTOT];

// ---------------------------------------------------------------------------
// K1: fused setup + sums (f32 accumulation, MLP-friendly). grid (41, 16), 256 thr.
//   x <  32 : image partial sums
//   x 32..39: clipped-patch partial sums (w,b computed inline)
//   x == 40 : per-box geometry + g_w/g_bj
// ---------------------------------------------------------------------------
__global__ void k_sums(const float* __restrict__ images,
                       const float* __restrict__ patch,
                       const float* __restrict__ boxes,
                       const float* __restrict__ scale_p) {
    int b = blockIdx.y, g = blockIdx.x;

    if (g == 40) {
        int n = threadIdx.x;
        if (n == 0) {
            float w[3], bb[3];
            wb_for(b, w, bb);
            #pragma unroll
            for (int c = 0; c < 3; c++) { g_w[b][c] = w[c]; g_bj[b][c] = bb[c]; }
        }
        if (n < Nbox) {
            float scale = scale_p[0];
            uint32_t ib0, ib1, kl0, kl1;
            tf2x32(0u, 42u, 0u, (uint32_t)b, ib0, ib1);
            tf2x32(ib0, ib1, 0u, 2u, kl0, kl1);
            uint32_t kn0, kn1;
            tf2x32(kl0, kl1, 0u, (uint32_t)n, kn0, kn1);
            uint32_t k10, k11, k20, k21, k30, k31;
            tf2x32(kn0, kn1, 0u, 0u, k10, k11);
            tf2x32(kn0, kn1, 0u, 1u, k20, k21);
            tf2x32(kn0, kn1, 0u, 2u, k30, k31);

            const float MAXA = (float)(20.0 * 3.14159265358979323846 / 180.0);
            float angle  = juniform(k10, k11, 0ull, -MAXA, MAXA);
            float bright = juniform(k30, k31, 0ull, -0.3f, 0.3f);

            const float* bx = boxes + ((size_t)b * Nbox + n) * 4;
            float ymin = bx[0], xmin = bx[1], ymax = bx[2], xmax = bx[3];
            float h  = ymax - ymin;
            float ww = xmax - xmin;
            float longer = fmaxf(h, ww);
            float ps   = floorf(longer * scale);
            float diag = fminf(sqrtf(2.0f) * ps, (float)Wim);
            float oy = ymin + h * 0.5f;
            float ox = xmin + ww * 0.5f;
            float y0 = fmaxf(oy - diag * 0.5f, 0.0f);
            float x0 = fmaxf(ox - diag * 0.5f, 0.0f);
            y0 = (y0 + diag > (float)Him) ? ((float)Him - diag) : y0;
            x0 = (x0 + diag > (float)Wim) ? ((float)Wim - diag) : x0;
            float phi   = fmaxf(floorf(ps), 1.0f);
            float diagi = floorf(diag);

            Geo gg;
            gg.y0i = floorf(y0); gg.x0i = floorf(x0);
            gg.diagi = diagi; gg.phi = phi;
            gg.cc  = (diagi - 1.0f) * 0.5f;
            gg.top = floorf((diagi - phi) * 0.5f);
            gg.r   = 300.0f / phi;
            gg.ca  = cosf(angle);
            gg.sa  = sinf(angle);
            gg.bright = bright;
            gg.k2a = k20; gg.k2b = k21;
            gg.valid = (phi * phi > 60.0f) ? 1 : 0;
            gg.pad = 0;
            g_geo[b][n] = gg;
        }
        return;
    }

    float acc = 0.0f;
    if (g < 32) {
        // 2.4 MB chunk, 256 thr, 2x float4 per iteration, 8 independent f32 accs
        const size_t IMG = (size_t)Him * Wim * 3;
        size_t base = (size_t)b * IMG + (size_t)g * (IMG / 32);
        const float4* src = (const float4*)(images + base);
        const int nvec = (int)((IMG / 32) / 4);     // 9600 float4s
        float a0 = 0.f, a1 = 0.f, a2 = 0.f, a3 = 0.f;
        float a4 = 0.f, a5 = 0.f, a6 = 0.f, a7 = 0.f;
        int i = threadIdx.x;
        // nvec/256 = 37.5 -> uneven; loop pairs, tail handled below
        for (; i + 256 < nvec; i += 512) {
            float4 v = src[i];
            float4 u = src[i + 256];
            a0 += v.x; a1 += v.y; a2 += v.z; a3 += v.w;
            a4 += u.x; a5 += u.y; a6 += u.z; a7 += u.w;
        }
        if (i < nvec) {
            float4 v = src[i];
            a0 += v.x; a1 += v.y; a2 += v.z; a3 += v.w;
        }
        acc = ((a0 + a1) + (a2 + a3)) + ((a4 + a5) + (a6 + a7));
    } else {
        float w[3], bb[3];
        wb_for(b, w, bb);
        int gp = g - 32;
        int chunk = PTOT / 8;                        // 33750
        int base = gp * chunk;
        float a0 = 0.f, a1 = 0.f;
        int i = base + threadIdx.x;
        int end = base + chunk;
        for (; i + 256 < end; i += 512) {
            int c0 = i % 3;
            int c1 = (i + 256) % 3;
            a0 += fminf(fmaxf(w[c0] * patch[i] + bb[c0], -1.0f), 1.0f);
            a1 += fminf(fmaxf(w[c1] * patch[i + 256] + bb[c1], -1.0f), 1.0f);
        }
        if (i < end) {
            int c = i % 3;
            a0 += fminf(fmaxf(w[c] * patch[i] + bb[c], -1.0f), 1.0f);
        }
        acc = a0 + a1;
    }
    __shared__ float sh[256];
    sh[threadIdx.x] = acc;
    __syncthreads();
    for (int s = 128; s > 0; s >>= 1) {
        if (threadIdx.x < s) sh[threadIdx.x] += sh[threadIdx.x + s];
        __syncthreads();
    }
    if (threadIdx.x == 0) {
        if (g < 32) g_isum[b][g] = sh[0];
        else        g_psum[b][g - 32] = sh[0];
    }
}

// ---------------------------------------------------------------------------
// K2: pre-adjust patch per image: clip(clip(w*p+b) + s). Inline s-finalize.
// grid (88, 16), 256 thr; 12 floats (4 px) per thread, float4 I/O.
// ---------------------------------------------------------------------------
__global__ void k_adj(const float* __restrict__ patch) {
    int b = blockIdx.y;
    __shared__ float ss;
    if (threadIdx.x == 0) {
        float si = 0.0f;
        #pragma unroll
        for (int g = 0; g < 32; g++) si += g_isum[b][g];
        float sp = 0.0f;
        #pragma unroll
        for (int g = 0; g < 8; g++) sp += g_psum[b][g];
        ss = si / 1228800.0f - sp / 270000.0f;
    }
    __syncthreads();
    float s = ss;
    float w0 = g_w[b][0], w1 = g_w[b][1], w2 = g_w[b][2];
    float b0 = g_bj[b][0], b1 = g_bj[b][1], b2 = g_bj[b][2];

    int i0 = (blockIdx.x * 256 + threadIdx.x) * 12;
    if (i0 >= PTOT) return;
    const float4* src = (const float4*)(patch + i0);
    float4* dst = (float4*)(&g_adjP[b][i0]);
    float4 v0 = src[0], v1 = src[1], v2 = src[2];

#define ADJ(x, wv, bv) fminf(fmaxf(fminf(fmaxf((wv)*(x)+(bv), -1.f), 1.f) + s, -1.f), 1.f)
    float4 r0, r1, r2;
    r0.x = ADJ(v0.x, w0, b0); r0.y = ADJ(v0.y, w1, b1);
    r0.z = ADJ(v0.z, w2, b2); r0.w = ADJ(v0.w, w0, b0);
    r1.x = ADJ(v1.x, w1, b1); r1.y = ADJ(v1.y, w2, b2);
    r1.z = ADJ(v1.z, w0, b0); r1.w = ADJ(v1.w, w1, b1);
    r2.x = ADJ(v2.x, w2, b2); r2.y = ADJ(v2.y, w0, b0);
    r2.z = ADJ(v2.z, w1, b1); r2.w = ADJ(v2.w, w2, b2);
#undef ADJ
    dst[0] = r0; dst[1] = r1; dst[2] = r2;
}

// ---------------------------------------------------------------------------
// K3: per-pixel last-writer resolve + compacted heavy phase.
// grid (20, 80, 16), block (32, 8).
// ---------------------------------------------------------------------------
__global__ void k_main(const float* __restrict__ images,
                       float* __restrict__ oimg,
                       float* __restrict__ omask) {
    __shared__ Geo   sg[Nbox];
    __shared__ float spy[256], spx[256];
    __shared__ float so0[256], so1[256], so2[256];
    __shared__ int   spk[256];
    __shared__ int   scnt;

    int b = blockIdx.z;
    int t = threadIdx.y * 32 + threadIdx.x;
    if (t < Nbox * 14)
        ((float*)sg)[t] = ((const float*)&g_geo[b][0])[t];
    if (t == 0) scnt = 0;
    __syncthreads();

    int x = blockIdx.x * 32 + threadIdx.x;
    int y = blockIdx.y * 8 + threadIdx.y;
    float tx0 = (float)(blockIdx.x * 32);
    float ty0 = (float)(blockIdx.y * 8);

    unsigned m = 0;
    #pragma unroll
    for (int n = 0; n < Nbox; n++) {
        const Geo& G = sg[n];
        bool ov = G.valid &&
                  (ty0 + 8.0f > G.y0i) && (ty0 < G.y0i + G.diagi) &&
                  (tx0 + 32.0f > G.x0i) && (tx0 < G.x0i + G.diagi);
        if (ov) m |= (1u << n);
    }

    size_t base = (((size_t)b * Him + y) * Wim + x) * 3;
    float o0 = images[base], o1 = images[base + 1], o2 = images[base + 2];

    if (m == 0) {   // block-uniform: no box touches this tile
        oimg[base] = o0; oimg[base + 1] = o1; oimg[base + 2] = o2;
        omask[base] = 0.f; omask[base + 1] = 0.f; omask[base + 2] = 0.f;
        return;
    }

    // ---- phase 1: resolve last-writer box per pixel ----
    int V = -1;
    float vpy = 0.f, vpx = 0.f;
    float fy_ = (float)y, fx_ = (float)x;
    while (m) {
        int n = __ffs(m) - 1;
        m &= m - 1;
        const Geo& G = sg[n];
        float u = fy_ - G.y0i;
        float v = fx_ - G.x0i;
        if (u >= 0.f && v >= 0.f && u < G.diagi && v < G.diagi) {
            float um = u - G.cc, vm = v - G.cc;
            float py = G.cc + G.ca * um - G.sa * vm - G.top;
            float px = G.cc + G.sa * um + G.ca * vm - G.top;
            float lim = G.phi - 1.0f;
            if (py >= 0.f && py <= lim && px >= 0.f && px <= lim) {
                V = n; vpy = py; vpx = px;
            }
        }
    }

    bool heavy = (V >= 0);
    if (!heavy) {
        oimg[base] = o0; oimg[base + 1] = o1; oimg[base + 2] = o2;
        omask[base] = 0.f; omask[base + 1] = 0.f; omask[base + 2] = 0.f;
    } else {
        so0[t] = o0; so1[t] = o1; so2[t] = o2;
    }

    // warp-aggregated enqueue
    unsigned wm = __ballot_sync(0xffffffffu, heavy);
    int lane = threadIdx.x;
    int wbase = 0;
    if (wm) {
        if (lane == 0) wbase = atomicAdd(&scnt, __popc(wm));
        wbase = __shfl_sync(0xffffffffu, wbase, 0);
        if (heavy) {
            int pos = wbase + __popc(wm & ((1u << lane) - 1u));
            spy[pos] = vpy; spx[pos] = vpx;
            spk[pos] = (t << 4) | V;
        }
    }
    __syncthreads();

    // ---- phase 2: dense processing of compacted heavy pixels ----
    int cnt = scnt;
    if (t < cnt) {
        int pk = spk[t];
        int p  = pk >> 4;
        const Geo& G = sg[pk & 15];
        float py = spy[t], px = spx[t];
        int yy = blockIdx.y * 8 + (p >> 5);
        int xx = blockIdx.x * 32 + (p & 31);

        float sy = (py + 0.5f) * G.r - 0.5f;
        float sx = (px + 0.5f) * G.r - 0.5f;
        float fy = floorf(sy), fx = floorf(sx);
        float wy = sy - fy, wx = sx - fx;
        int y0c = min(max((int)fy, 0), PHp - 1);
        int y1c = min(y0c + 1, PHp - 1);
        int x0c = min(max((int)fx, 0), PWp - 1);
        int x1c = min(x0c + 1, PWp - 1);
        const float* P = g_adjP[b];
        int o00 = (y0c * PWp + x0c) * 3;
        int o01 = (y0c * PWp + x1c) * 3;
        int o10 = (y1c * PWp + x0c) * 3;
        int o11 = (y1c * PWp + x1c) * 3;

        uint32_t nb = ((uint32_t)yy * (uint32_t)Wim + (uint32_t)xx) * 3u;
        uint32_t bits[3];
        tf3(G.k2a, G.k2b, nb, bits);

        float omy = 1.0f - wy, omx = 1.0f - wx;
        float w00 = omy * omx, w01 = omy * wx, w10 = wy * omx, w11 = wy * wx;
        float res[3];
        #pragma unroll
        for (int c = 0; c < 3; c++) {
            float samp = P[o00 + c] * w00 + P[o01 + c] * w01
                       + P[o10 + c] * w10 + P[o11 + c] * w11;
            float noise = fmaxf(-0.1f, fmaf(bits_to_unit(bits[c]), 0.2f, -0.1f));
            res[c] = fminf(fmaxf(samp + noise + G.bright, -1.0f), 1.0f);
        }

        size_t hb = (((size_t)b * Him + yy) * Wim + xx) * 3;
        oimg[hb]     = res[0]; oimg[hb + 1]  = res[1]; oimg[hb + 2]  = res[2];
        omask[hb]    = so0[p] - res[0];
        omask[hb + 1] = so1[p] - res[1];
        omask[hb + 2] = so2[p] - res[2];
    }
}

// ---------------------------------------------------------------------------
extern "C" void kernel_launch(void* const* d_in, const int* in_sizes, int n_in,
                              void* d_out, int out_size) {
    const float* boxes  = (const float*)d_in[0];
    const float* images = (const float*)d_in[1];
    const float* patch  = (const float*)d_in[2];
    const float* scale  = (const float*)d_in[3];
    float* out   = (float*)d_out;
    float* omask = out + (size_t)Bimg * Him * Wim * 3;

    k_sums<<<dim3(41, 16), 256>>>(images, patch, boxes, scale);
    k_adj<<<dim3(88, 16), 256>>>(patch);
    k_main<<<dim3(20, 80, 16), dim3(32, 8)>>>(images, out, omask);

    (void)in_sizes; (void)n_in; (void)out_size;
}